// round 10
// baseline (speedup 1.0000x reference)
#include <cuda_runtime.h>
#include <cuda_bf16.h>
#include <math.h>
#include <cstdint>

// Problem dims
#define BB   64
#define N1   1152
#define PP   8
#define N2   128
#define DD   16
#define NDD  2048

#define I_B  64                 // i's per block
#define BG   8                  // b's per block
#define NBI  (N1 / I_B)         // 18
#define NBB  (BB / BG)          // 8
#define NT   256                // 8 warps; CTA covers ONE n-half (64 n)

typedef unsigned long long ull;

// Scratch (no allocations allowed -> device globals)
__device__ float  g_partial[NBI * BB * NDD];     // 9.44 MB per-(iblock,b) partials
__device__ float  g_v0[BB * NDD];                // squashed v after iteration 0
__device__ float4 g_W2[(size_t)N1 * 4096];       // 75.5 MB repacked W (d-pair layout)

// ---------------- f32x2 helpers (2x fp32 throughput on sm_103a) -------------
__device__ __forceinline__ ull d_fma2(ull a, ull b, ull c) {
    ull r; asm("fma.rn.f32x2 %0, %1, %2, %3;" : "=l"(r) : "l"(a), "l"(b), "l"(c)); return r;
}
__device__ __forceinline__ ull d_mul2(ull a, ull b) {
    ull r; asm("mul.rn.f32x2 %0, %1, %2;" : "=l"(r) : "l"(a), "l"(b)); return r;
}
__device__ __forceinline__ ull d_add2(ull a, ull b) {
    ull r; asm("add.rn.f32x2 %0, %1, %2;" : "=l"(r) : "l"(a), "l"(b)); return r;
}
__device__ __forceinline__ ull d_dup(float x) {
    ull r; unsigned u = __float_as_uint(x);
    asm("mov.b64 %0, {%1, %2};" : "=l"(r) : "r"(u), "r"(u)); return r;
}
__device__ __forceinline__ ull d_pack(float lo, float hi) {
    ull r; unsigned a = __float_as_uint(lo), b = __float_as_uint(hi);
    asm("mov.b64 %0, {%1, %2};" : "=l"(r) : "r"(a), "r"(b)); return r;
}
__device__ __forceinline__ float d_hadd(ull a) {
    unsigned lo, hi; asm("mov.b64 {%0, %1}, %2;" : "=r"(lo), "=r"(hi) : "l"(a));
    return __uint_as_float(lo) + __uint_as_float(hi);
}
__device__ __forceinline__ void d_unpack(ull a, float& lo, float& hi) {
    unsigned x, y; asm("mov.b64 {%0, %1}, %2;" : "=r"(x), "=r"(y) : "l"(a));
    lo = __uint_as_float(x); hi = __uint_as_float(y);
}

// ---------------- cluster / mbarrier helpers --------------------------------
__device__ __forceinline__ uint32_t smaddr(const void* p) {
    uint32_t a;
    asm("{ .reg .u64 t; cvta.to.shared.u64 t, %1; cvt.u32.u64 %0, t; }" : "=r"(a) : "l"(p));
    return a;
}
__device__ __forceinline__ uint32_t cluster_rank() {
    uint32_t r; asm("mov.u32 %0, %%cluster_ctarank;" : "=r"(r)); return r;
}
__device__ __forceinline__ void mbar_init1(uint32_t addr) {
    asm volatile("mbarrier.init.shared.b64 [%0], %1;" :: "r"(addr), "r"(1u) : "memory");
}
__device__ __forceinline__ void peer_st_v4(uint32_t laddr, uint32_t peer,
                                           float a, float b, float c, float d) {
    asm volatile(
        "{ .reg .b32 ra; mapa.shared::cluster.u32 ra, %0, %1;\n\t"
        "st.shared::cluster.v4.b32 [ra], {%2, %3, %4, %5}; }"
        :: "r"(laddr), "r"(peer),
           "r"(__float_as_uint(a)), "r"(__float_as_uint(b)),
           "r"(__float_as_uint(c)), "r"(__float_as_uint(d)) : "memory");
}
__device__ __forceinline__ void peer_arrive(uint32_t lmbar, uint32_t peer) {
    asm volatile(
        "{ .reg .b32 ra; mapa.shared::cluster.u32 ra, %0, %1;\n\t"
        "mbarrier.arrive.release.cluster.shared::cluster.b64 _, [ra]; }"
        :: "r"(lmbar), "r"(peer) : "memory");
}
__device__ __forceinline__ void mbar_wait_cluster(uint32_t mbar, uint32_t parity) {
    uint32_t done;
    asm volatile(
        "{ .reg .pred p;\n\t"
        "mbarrier.try_wait.parity.acquire.cluster.shared::cta.b64 p, [%1], %2;\n\t"
        "selp.b32 %0, 1, 0, p; }" : "=r"(done) : "r"(mbar), "r"(parity) : "memory");
    while (!done) {
        asm volatile(
            "{ .reg .pred p;\n\t"
            "mbarrier.try_wait.parity.acquire.cluster.shared::cta.b64 p, [%1], %2, 0x989680;\n\t"
            "selp.b32 %0, 1, 0, p; }" : "=r"(done) : "r"(mbar), "r"(parity) : "memory");
    }
}
#define CLUSTER_SYNC() do { \
    asm volatile("barrier.cluster.arrive.aligned;" ::: "memory"); \
    asm volatile("barrier.cluster.wait.aligned;" ::: "memory");   \
} while (0)

// ---------------------------------------------------------------------------
// Repack W (layout unchanged): float4 idx = i*4096 + ow*256 + p*32 + l holds
//   { W[i,n,dq+0,p], W[i,n,dq+1,p], W[i,n,dq+2,p], W[i,n,dq+3,p] }
// with n = 8*ow + (l>>2), dq = (l&3)*4, ow in [0,16).
// Main pass uses ow = 8*half + w  (half = cluster rank = n-half).
// ---------------------------------------------------------------------------
__global__ __launch_bounds__(256) void repack_W(const float* __restrict__ W)
{
    const size_t idx = (size_t)blockIdx.x * 256 + threadIdx.x;
    const int l  = (int)(idx & 31);
    const int p  = (int)((idx >> 5) & 7);
    const int ow = (int)((idx >> 8) & 15);
    const size_t i = idx >> 12;
    const int n  = ow * 8 + (l >> 2);
    const int dq = (l & 3) * 4;
    const float* src = W + i * 16384 + n * 128 + p;
    float4 v;
    v.x = src[(dq + 0) * 8]; v.y = src[(dq + 1) * 8];
    v.z = src[(dq + 2) * 8]; v.w = src[(dq + 3) * 8];
    g_W2[idx] = v;
}

// ---------------------------------------------------------------------------
// smem layout (bytes)
#define SM_X2    0        // 4096 ull  = 32768  (x duplicated as f32x2)
#define SM_V0    32768    // 8192 f    = 32768  (ROUTE: own n-half of v0)
#define SM_RED   65536    // 2*8*8 f   = 512    (warp softmax partials, dbl-buf)
#define SM_SREM  66048    // 2*8 f     = 64     (peer's half-sums, dbl-buf)
#define SM_MBAR  66112    // 2 ull     = 16
#define SMEM_ROUTE 66176
#define SMEM_P0    32768

// One kernel, two modes. Cluster (2,1,1): rank = n-half. 256 thr, 2 CTA/SM.
// Warp w owns 8 n of its half; lane: n = 64*half + 8w + (l>>2), dq=(l&3)*4.
// ROUTE: per-ii local softmax sums + 8-float DSMEM exchange with the peer
// n-half (mbarrier, double-buffered), then c = e / (Sloc+Srem).
// ---------------------------------------------------------------------------
template<bool ROUTE>
__global__ __launch_bounds__(NT, 2) __cluster_dims__(2, 1, 1)
void caps_pass(const float* __restrict__ x, const float* __restrict__ v0in)
{
    extern __shared__ char smraw[];
    ull*   x2   = (ull*)(smraw + SM_X2);
    float* v0s  = (float*)(smraw + SM_V0);
    float* red  = (float*)(smraw + SM_RED);
    float* Srem = (float*)(smraw + SM_SREM);

    const int tid  = threadIdx.x;
    const int w    = tid >> 5;
    const int l    = tid & 31;
    const int half = blockIdx.x;                // == cluster rank
    const int ib0  = blockIdx.y * I_B;
    const int b0   = blockIdx.z * BG;
    const int ow   = half * 8 + w;
    const int nl   = w * 8 + (l >> 2);          // n within this half
    const int dq   = (l & 3) * 4;

    uint32_t mb0 = 0, srem0 = 0, peer = 0;
    if (ROUTE) {
        peer  = cluster_rank() ^ 1u;
        mb0   = smaddr(smraw + SM_MBAR);
        srem0 = smaddr(smraw + SM_SREM);
        if (tid == 0) { mbar_init1(mb0); mbar_init1(mb0 + 8); }
    }

    // stage x duplicated as f32x2: x2[bb*512 + ii*8 + p]
    for (int t = tid; t < BG * I_B * PP; t += NT) {
        const int bb = t >> 9, rem = t & 511;
        x2[t] = d_dup(x[(size_t)(b0 + bb) * (N1 * PP) + (size_t)ib0 * PP + rem]);
    }
    if (ROUTE) {
        for (int t = tid; t < BG * 1024; t += NT) {       // own half of v0
            const int bb = t >> 10, rem = t & 1023;
            v0s[t] = v0in[(size_t)(b0 + bb) * NDD + half * 1024 + rem];
        }
    }
    __syncthreads();
    if (ROUTE) CLUSTER_SYNC();                  // peer mbarriers live before use

    ull sacc[BG][2];
#pragma unroll
    for (int bb = 0; bb < BG; ++bb) { sacc[bb][0] = 0ull; sacc[bb][1] = 0ull; }

#pragma unroll 1
    for (int ii = 0; ii < I_B; ++ii) {
        const ulonglong2* Wp = (const ulonglong2*)(g_W2
            + (((size_t)(ib0 + ii)) << 12) + (ow << 8));
        ulonglong2 wv[8];
#pragma unroll
        for (int p = 0; p < 8; ++p) wv[p] = Wp[p * 32 + l];   // half-W_i, MLP=8

        if (!ROUTE) {
#pragma unroll
            for (int bb = 0; bb < BG; ++bb) {
                const ulonglong2* xq = (const ulonglong2*)(x2 + bb * 512 + ii * 8);
                const ulonglong2 x01 = xq[0], x23 = xq[1], x45 = xq[2], x67 = xq[3];
                ull a = sacc[bb][0], b = sacc[bb][1];
                a = d_fma2(x01.x, wv[0].x, a); b = d_fma2(x01.x, wv[0].y, b);
                a = d_fma2(x01.y, wv[1].x, a); b = d_fma2(x01.y, wv[1].y, b);
                a = d_fma2(x23.x, wv[2].x, a); b = d_fma2(x23.x, wv[2].y, b);
                a = d_fma2(x23.y, wv[3].x, a); b = d_fma2(x23.y, wv[3].y, b);
                a = d_fma2(x45.x, wv[4].x, a); b = d_fma2(x45.x, wv[4].y, b);
                a = d_fma2(x45.y, wv[5].x, a); b = d_fma2(x45.y, wv[5].y, b);
                a = d_fma2(x67.x, wv[6].x, a); b = d_fma2(x67.x, wv[6].y, b);
                a = d_fma2(x67.y, wv[7].x, a); b = d_fma2(x67.y, wv[7].y, b);
                sacc[bb][0] = a; sacc[bb][1] = b;
            }
        } else {
            const int buf = ii & 1;
            ull pr[BG][2];
#pragma unroll
            for (int bb = 0; bb < BG; ++bb) {
                const ulonglong2* xq = (const ulonglong2*)(x2 + bb * 512 + ii * 8);
                const ulonglong2 x01 = xq[0], x23 = xq[1], x45 = xq[2], x67 = xq[3];
                ull a = d_mul2(x01.x, wv[0].x);
                ull b = d_mul2(x01.x, wv[0].y);
                a = d_fma2(x01.y, wv[1].x, a); b = d_fma2(x01.y, wv[1].y, b);
                a = d_fma2(x23.x, wv[2].x, a); b = d_fma2(x23.x, wv[2].y, b);
                a = d_fma2(x23.y, wv[3].x, a); b = d_fma2(x23.y, wv[3].y, b);
                a = d_fma2(x45.x, wv[4].x, a); b = d_fma2(x45.x, wv[4].y, b);
                a = d_fma2(x45.y, wv[5].x, a); b = d_fma2(x45.y, wv[5].y, b);
                a = d_fma2(x67.x, wv[6].x, a); b = d_fma2(x67.x, wv[6].y, b);
                a = d_fma2(x67.y, wv[7].x, a); b = d_fma2(x67.y, wv[7].y, b);
                pr[bb][0] = a; pr[bb][1] = b;

                // agreement + exp + warp sum over this warp's 8 n
                const float4 vv = *(const float4*)&v0s[bb * 1024 + nl * DD + dq];
                const ull t = d_fma2(a, d_pack(vv.x, vv.y), d_mul2(b, d_pack(vv.z, vv.w)));
                float r = d_hadd(t);
                r += __shfl_xor_sync(0xFFFFFFFFu, r, 1);
                r += __shfl_xor_sync(0xFFFFFFFFu, r, 2);          // full 16-d dot
                const float e = __expf(r);                        // |r| small, safe
                float S = e;
                S += __shfl_xor_sync(0xFFFFFFFFu, S, 4);
                S += __shfl_xor_sync(0xFFFFFFFFu, S, 8);
                S += __shfl_xor_sync(0xFFFFFFFFu, S, 16);         // sum of 8 n
                if (l == 0) red[(buf * 8 + w) * 8 + bb] = S;
                const ull ed = d_dup(e);
                pr[bb][0] = d_mul2(pr[bb][0], ed);                // fold e into pred
                pr[bb][1] = d_mul2(pr[bb][1], ed);
            }
            __syncthreads();                                      // one barrier per ii

            // Sloc[bb] = sum over 8 warps (broadcast LDS.128 + f32x2 adds)
            ull z01 = 0ull, z23 = 0ull, z45 = 0ull, z67 = 0ull;
#pragma unroll
            for (int k = 0; k < 8; ++k) {
                const ulonglong2* rp = (const ulonglong2*)&red[(buf * 8 + k) * 8];
                const ulonglong2 a = rp[0], b = rp[1];
                z01 = d_add2(z01, a.x); z23 = d_add2(z23, a.y);
                z45 = d_add2(z45, b.x); z67 = d_add2(z67, b.y);
            }

            // exchange half-sums with peer n-half (8 floats, dbl-buffered)
            if (tid == 0) {
                float s0, s1, s2, s3, s4, s5, s6, s7;
                d_unpack(z01, s0, s1); d_unpack(z23, s2, s3);
                d_unpack(z45, s4, s5); d_unpack(z67, s6, s7);
                const uint32_t dst = srem0 + buf * 32;
                peer_st_v4(dst,      peer, s0, s1, s2, s3);
                peer_st_v4(dst + 16, peer, s4, s5, s6, s7);
                peer_arrive(mb0 + buf * 8, peer);
            }
            mbar_wait_cluster(mb0 + buf * 8, (ii >> 1) & 1);

            const ulonglong2* sp = (const ulonglong2*)&Srem[buf * 8];
            const ulonglong2 q0 = sp[0], q1 = sp[1];
            z01 = d_add2(z01, q0.x); z23 = d_add2(z23, q0.y);
            z45 = d_add2(z45, q1.x); z67 = d_add2(z67, q1.y);

            float Z[8];
            d_unpack(z01, Z[0], Z[1]); d_unpack(z23, Z[2], Z[3]);
            d_unpack(z45, Z[4], Z[5]); d_unpack(z67, Z[6], Z[7]);
#pragma unroll
            for (int bb = 0; bb < BG; ++bb) {
                const ull cd = d_dup(__fdividef(1.0f, Z[bb]));    // c = e / Z
                sacc[bb][0] = d_fma2(cd, pr[bb][0], sacc[bb][0]);
                sacc[bb][1] = d_fma2(cd, pr[bb][1], sacc[bb][1]);
            }
        }
    }

    // write per-(iblock,b) partials for this half's n
#pragma unroll
    for (int bb = 0; bb < BG; ++bb) {
        float4 o;
        d_unpack(sacc[bb][0], o.x, o.y);
        d_unpack(sacc[bb][1], o.z, o.w);
        float* gp = g_partial + ((size_t)blockIdx.y * BB + (b0 + bb)) * NDD
                  + (half * 64 + nl) * DD + dq;
        *(float4*)gp = o;
    }
    if (ROUTE) CLUSTER_SYNC();       // no CTA exits while peer ops in flight
}

// ---------------------------------------------------------------------------
// Reduce the NBI partials, scale, squash, write out.
// 4 lanes per (b,n) row; quad shuffles for the norm.
// ---------------------------------------------------------------------------
__global__ __launch_bounds__(256) void reduce_squash_kernel(float* __restrict__ out, float scale)
{
    const int t = blockIdx.x * 256 + threadIdx.x;
    const int r = t >> 2;
    const int quad = t & 3;

    float4 s = make_float4(0.f, 0.f, 0.f, 0.f);
#pragma unroll 3
    for (int blk = 0; blk < NBI; ++blk) {
        const float4 a = *(const float4*)(g_partial
            + ((size_t)blk * (BB * N2) + r) * DD + quad * 4);
        s.x += a.x; s.y += a.y; s.z += a.z; s.w += a.w;
    }
    s.x *= scale; s.y *= scale; s.z *= scale; s.w *= scale;

    float sq = s.x * s.x + s.y * s.y + s.z * s.z + s.w * s.w;
    sq += __shfl_xor_sync(0xFFFFFFFFu, sq, 1);
    sq += __shfl_xor_sync(0xFFFFFFFFu, sq, 2);

    const float norm = sqrtf(sq + 1.1920929e-7f);
    const float f = sq / ((1.0f + sq) * norm);
    *(float4*)(out + (size_t)r * DD + quad * 4) =
        make_float4(f * s.x, f * s.y, f * s.z, f * s.w);
}

// ---------------------------------------------------------------------------
extern "C" void kernel_launch(void* const* d_in, const int* in_sizes, int n_in,
                              void* d_out, int out_size)
{
    const float* x = (const float*)d_in[0];
    const float* W = (const float*)d_in[1];
    if (n_in >= 2 && in_sizes[0] > in_sizes[1]) {   // safety: x is the smaller tensor
        const float* t = x; x = W; W = t;
    }
    float* out = (float*)d_out;

    float* d_v0;
    cudaGetSymbolAddress((void**)&d_v0, g_v0);

    cudaFuncSetAttribute(caps_pass<true>,
                         cudaFuncAttributeMaxDynamicSharedMemorySize, SMEM_ROUTE);

    // repack W into d-pair warp-coalesced layout
    repack_W<<<(int)(((size_t)N1 * 4096) / 256), 256>>>(W);

    dim3 grid(2, NBI, NBB);   // (n-half cluster, i-block, b-block) = 288 CTAs

    // iteration 0: uniform coupling -> s0 = (1/128) * sum_i pred
    caps_pass<false><<<grid, NT, SMEM_P0>>>(x, nullptr);
    reduce_squash_kernel<<<128, 256>>>(d_v0, 1.0f / 128.0f);

    // iteration 1: softmax(agreement) routing, final squash -> output
    caps_pass<true><<<grid, NT, SMEM_ROUTE>>>(x, d_v0);
    reduce_squash_kernel<<<128, 256>>>(out, 1.0f);
}

// round 14
// speedup vs baseline: 1.4335x; 1.4335x over previous
#include <cuda_runtime.h>
#include <cuda_bf16.h>
#include <math.h>
#include <cstdint>

// Problem dims
#define BB   64
#define N1   1152
#define PP   8
#define N2   128
#define DD   16
#define NDD  2048

#define I_B  64                 // i's per block
#define BG   8                  // b's per block
#define NBI  (N1 / I_B)         // 18
#define NBB  (BB / BG)          // 8
#define NT   256                // 8 warps; CTA covers one n-half (64 n)

typedef unsigned long long ull;

// Scratch (no allocations allowed -> device globals)
__device__ float  g_partial[NBI * BB * NDD];     // 9.44 MB per-(iblock,b) partials
__device__ float  g_v0[BB * NDD];                // squashed v after iteration 0
__device__ float  g_Zh[2 * BB * N1];             // per-half softmax denominators
__device__ float4 g_W2[(size_t)N1 * 4096];       // 75.5 MB repacked W (d-pair layout)

// ---------------- f32x2 helpers (2x fp32 throughput on sm_103a) -------------
__device__ __forceinline__ ull d_fma2(ull a, ull b, ull c) {
    ull r; asm("fma.rn.f32x2 %0, %1, %2, %3;" : "=l"(r) : "l"(a), "l"(b), "l"(c)); return r;
}
__device__ __forceinline__ ull d_mul2(ull a, ull b) {
    ull r; asm("mul.rn.f32x2 %0, %1, %2;" : "=l"(r) : "l"(a), "l"(b)); return r;
}
__device__ __forceinline__ ull d_dup(float x) {
    ull r; unsigned u = __float_as_uint(x);
    asm("mov.b64 %0, {%1, %2};" : "=l"(r) : "r"(u), "r"(u)); return r;
}
__device__ __forceinline__ ull d_pack(float lo, float hi) {
    ull r; unsigned a = __float_as_uint(lo), b = __float_as_uint(hi);
    asm("mov.b64 %0, {%1, %2};" : "=l"(r) : "r"(a), "r"(b)); return r;
}
__device__ __forceinline__ float d_hadd(ull a) {
    unsigned lo, hi; asm("mov.b64 {%0, %1}, %2;" : "=r"(lo), "=r"(hi) : "l"(a));
    return __uint_as_float(lo) + __uint_as_float(hi);
}
__device__ __forceinline__ void d_unpack(ull a, float& lo, float& hi) {
    unsigned x, y; asm("mov.b64 {%0, %1}, %2;" : "=r"(x), "=r"(y) : "l"(a));
    lo = __uint_as_float(x); hi = __uint_as_float(y);
}

// ---------------------------------------------------------------------------
// Repack W: float4 idx = i*4096 + ow*256 + p*32 + l holds
//   { W[i,n,dq+0,p], W[i,n,dq+1,p], W[i,n,dq+2,p], W[i,n,dq+3,p] }
// with n = 8*ow + (l>>2), dq = (l&3)*4, ow in [0,16).
// Main passes use ow = 8*half + w.
// ---------------------------------------------------------------------------
__global__ __launch_bounds__(256) void repack_W(const float* __restrict__ W)
{
    const size_t idx = (size_t)blockIdx.x * 256 + threadIdx.x;
    const int l  = (int)(idx & 31);
    const int p  = (int)((idx >> 5) & 7);
    const int ow = (int)((idx >> 8) & 15);
    const size_t i = idx >> 12;
    const int n  = ow * 8 + (l >> 2);
    const int dq = (l & 3) * 4;
    const float* src = W + i * 16384 + n * 128 + p;
    float4 v;
    v.x = src[(dq + 0) * 8]; v.y = src[(dq + 1) * 8];
    v.z = src[(dq + 2) * 8]; v.w = src[(dq + 3) * 8];
    g_W2[idx] = v;
}

// ---------------------------------------------------------------------------
// smem layout (bytes): x2 always; v0 for MODE>=1; then per-mode extras
#define SMO_X2   0        // 4096 ull  = 32768 (x duplicated as f32x2)
#define SMO_V0   32768    // 8192 f    = 32768 (own n-half of v0)
#define SMO_SZ   65536    // MODE 1: 64*8*8 f = 16384 (per-warp e-sums)
#define SMO_ZI   65536    // MODE 2: 512 f    = 2048  (precomputed 1/Z)
#define SMEM_M0  32768
#define SMEM_M1  81920
#define SMEM_M2  67584

// One streaming kernel, three modes, ZERO in-loop synchronization.
//   MODE 0: sacc += pred                       (iteration 0, uniform c)
//   MODE 1: Zh[b,i] = sum_{n in half} exp(<pred, v0>)   (denominator pass)
//   MODE 2: sacc += (e * 1/Z[b,i]) * pred      (weighted pass, Z precomputed)
// Warp w owns 8 n of its half; lane: n = 64*half + 8w + (l>>2), dq = (l&3)*4.
// ---------------------------------------------------------------------------
template<int MODE>
__global__ __launch_bounds__(NT, 2)
void caps_pass(const float* __restrict__ x, const float* __restrict__ v0in)
{
    extern __shared__ char smraw[];
    ull*   x2   = (ull*)(smraw + SMO_X2);
    float* v0s  = (float*)(smraw + SMO_V0);
    float* sZ   = (float*)(smraw + SMO_SZ);     // MODE 1
    float* zinv = (float*)(smraw + SMO_ZI);     // MODE 2

    const int tid  = threadIdx.x;
    const int w    = tid >> 5;
    const int l    = tid & 31;
    const int half = blockIdx.x;
    const int ib0  = blockIdx.y * I_B;
    const int b0   = blockIdx.z * BG;
    const int ow   = half * 8 + w;
    const int nl   = w * 8 + (l >> 2);          // n within this half
    const int dq   = (l & 3) * 4;

    // stage x duplicated as f32x2: x2[bb*512 + ii*8 + p]
    for (int t = tid; t < BG * I_B * PP; t += NT) {
        const int bb = t >> 9, rem = t & 511;
        x2[t] = d_dup(x[(size_t)(b0 + bb) * (N1 * PP) + (size_t)ib0 * PP + rem]);
    }
    if (MODE >= 1) {
        for (int t = tid; t < BG * 1024; t += NT) {       // own n-half of v0
            const int bb = t >> 10, rem = t & 1023;
            v0s[t] = v0in[(size_t)(b0 + bb) * NDD + half * 1024 + rem];
        }
    }
    if (MODE == 2) {
        for (int t = tid; t < I_B * BG; t += NT) {        // 1/Z for (ii, bb)
            const int ii = t >> 3, bb = t & 7;
            const size_t zi = (size_t)(b0 + bb) * N1 + (ib0 + ii);
            zinv[t] = __fdividef(1.0f, g_Zh[zi] + g_Zh[BB * N1 + zi]);
        }
    }
    __syncthreads();

    ull sacc[BG][2];
    if (MODE != 1) {
#pragma unroll
        for (int bb = 0; bb < BG; ++bb) { sacc[bb][0] = 0ull; sacc[bb][1] = 0ull; }
    }

#pragma unroll 1
    for (int ii = 0; ii < I_B; ++ii) {
        const ulonglong2* Wp = (const ulonglong2*)(g_W2
            + (((size_t)(ib0 + ii)) << 12) + (ow << 8));
        ulonglong2 wv[8];
#pragma unroll
        for (int p = 0; p < 8; ++p) wv[p] = Wp[p * 32 + l];   // half W_i, MLP=8

#pragma unroll
        for (int bb = 0; bb < BG; ++bb) {
            const ulonglong2* xq = (const ulonglong2*)(x2 + bb * 512 + ii * 8);
            const ulonglong2 x01 = xq[0], x23 = xq[1], x45 = xq[2], x67 = xq[3];

            ull a, b;
            if (MODE == 0) { a = sacc[bb][0]; b = sacc[bb][1];
                a = d_fma2(x01.x, wv[0].x, a); b = d_fma2(x01.x, wv[0].y, b);
            } else {
                a = d_mul2(x01.x, wv[0].x);    b = d_mul2(x01.x, wv[0].y);
            }
            a = d_fma2(x01.y, wv[1].x, a); b = d_fma2(x01.y, wv[1].y, b);
            a = d_fma2(x23.x, wv[2].x, a); b = d_fma2(x23.x, wv[2].y, b);
            a = d_fma2(x23.y, wv[3].x, a); b = d_fma2(x23.y, wv[3].y, b);
            a = d_fma2(x45.x, wv[4].x, a); b = d_fma2(x45.x, wv[4].y, b);
            a = d_fma2(x45.y, wv[5].x, a); b = d_fma2(x45.y, wv[5].y, b);
            a = d_fma2(x67.x, wv[6].x, a); b = d_fma2(x67.x, wv[6].y, b);
            a = d_fma2(x67.y, wv[7].x, a); b = d_fma2(x67.y, wv[7].y, b);

            if (MODE == 0) {
                sacc[bb][0] = a; sacc[bb][1] = b;
            } else {
                // agreement r = <pred, v0> over this lane's quad (full 16 d)
                const float4 vv = *(const float4*)&v0s[bb * 1024 + nl * DD + dq];
                const ull t = d_fma2(a, d_pack(vv.x, vv.y),
                                     d_mul2(b, d_pack(vv.z, vv.w)));
                float r = d_hadd(t);
                r += __shfl_xor_sync(0xFFFFFFFFu, r, 1);
                r += __shfl_xor_sync(0xFFFFFFFFu, r, 2);
                const float e = __expf(r);              // |r| bounded; no max-sub

                if (MODE == 1) {
                    float S = e;                        // sum of warp's 8 distinct n
                    S += __shfl_xor_sync(0xFFFFFFFFu, S, 4);
                    S += __shfl_xor_sync(0xFFFFFFFFu, S, 8);
                    S += __shfl_xor_sync(0xFFFFFFFFu, S, 16);
                    if (l == 0) sZ[ii * 64 + bb * 8 + w] = S;   // private slot
                } else {                                // MODE 2
                    const ull cd = d_dup(e * zinv[ii * 8 + bb]);
                    sacc[bb][0] = d_fma2(cd, a, sacc[bb][0]);
                    sacc[bb][1] = d_fma2(cd, b, sacc[bb][1]);
                }
            }
        }
    }

    if (MODE == 1) {
        __syncthreads();                                // only barrier in kernel
        for (int t = tid; t < I_B * BG; t += NT) {      // combine 8 warp sums
            const int ii = t >> 3, bb = t & 7;
            const float4* p4 = (const float4*)&sZ[ii * 64 + bb * 8];
            const float4 u = p4[0], v = p4[1];
            g_Zh[(size_t)half * (BB * N1) + (size_t)(b0 + bb) * N1 + (ib0 + ii)]
                = (u.x + u.y + u.z + u.w) + (v.x + v.y + v.z + v.w);
        }
    } else {
        // write per-(iblock,b) partials for this half's n
#pragma unroll
        for (int bb = 0; bb < BG; ++bb) {
            float4 o;
            d_unpack(sacc[bb][0], o.x, o.y);
            d_unpack(sacc[bb][1], o.z, o.w);
            float* gp = g_partial + ((size_t)blockIdx.y * BB + (b0 + bb)) * NDD
                      + (half * 64 + nl) * DD + dq;
            *(float4*)gp = o;
        }
    }
}

// ---------------------------------------------------------------------------
// Reduce the NBI partials, scale, squash, write out.
// 4 lanes per (b,n) row; quad shuffles for the norm.
// ---------------------------------------------------------------------------
__global__ __launch_bounds__(256) void reduce_squash_kernel(float* __restrict__ out, float scale)
{
    const int t = blockIdx.x * 256 + threadIdx.x;
    const int r = t >> 2;
    const int quad = t & 3;

    float4 s = make_float4(0.f, 0.f, 0.f, 0.f);
#pragma unroll 3
    for (int blk = 0; blk < NBI; ++blk) {
        const float4 a = *(const float4*)(g_partial
            + ((size_t)blk * (BB * N2) + r) * DD + quad * 4);
        s.x += a.x; s.y += a.y; s.z += a.z; s.w += a.w;
    }
    s.x *= scale; s.y *= scale; s.z *= scale; s.w *= scale;

    float sq = s.x * s.x + s.y * s.y + s.z * s.z + s.w * s.w;
    sq += __shfl_xor_sync(0xFFFFFFFFu, sq, 1);
    sq += __shfl_xor_sync(0xFFFFFFFFu, sq, 2);

    const float norm = sqrtf(sq + 1.1920929e-7f);
    const float f = sq / ((1.0f + sq) * norm);
    *(float4*)(out + (size_t)r * DD + quad * 4) =
        make_float4(f * s.x, f * s.y, f * s.z, f * s.w);
}

// ---------------------------------------------------------------------------
extern "C" void kernel_launch(void* const* d_in, const int* in_sizes, int n_in,
                              void* d_out, int out_size)
{
    const float* x = (const float*)d_in[0];
    const float* W = (const float*)d_in[1];
    if (n_in >= 2 && in_sizes[0] > in_sizes[1]) {   // safety: x is the smaller tensor
        const float* t = x; x = W; W = t;
    }
    float* out = (float*)d_out;

    float* d_v0;
    cudaGetSymbolAddress((void**)&d_v0, g_v0);

    cudaFuncSetAttribute(caps_pass<1>,
                         cudaFuncAttributeMaxDynamicSharedMemorySize, SMEM_M1);
    cudaFuncSetAttribute(caps_pass<2>,
                         cudaFuncAttributeMaxDynamicSharedMemorySize, SMEM_M2);

    // repack W into d-pair warp-coalesced layout
    repack_W<<<(int)(((size_t)N1 * 4096) / 256), 256>>>(W);

    dim3 grid(2, NBI, NBB);   // (n-half, i-block, b-block) = 288 CTAs

    // iteration 0: uniform coupling -> s0 = (1/128) * sum_i pred
    caps_pass<0><<<grid, NT, SMEM_M0>>>(x, nullptr);
    reduce_squash_kernel<<<128, 256>>>(d_v0, 1.0f / 128.0f);

    // iteration 1 split: Z pass, then barrier-free weighted pass
    caps_pass<1><<<grid, NT, SMEM_M1>>>(x, d_v0);
    caps_pass<2><<<grid, NT, SMEM_M2>>>(x, d_v0);
    reduce_squash_kernel<<<128, 256>>>(out, 1.0f);
}